// round 1
// baseline (speedup 1.0000x reference)
#include <cuda_runtime.h>
#include <math.h>

// ---------------- problem constants ----------------
#define Bb   64
#define Nn   1024
#define DIN  32
#define DOUT 64
#define CIN  96        // DIN + DOUT
#define KSUP 3
#define EDm  16
#define OG   128       // gate output (2*DOUT)
#define OU   64        // update output
#define KI   288       // KSUP * CIN

// ---------------- scratch (device globals; no runtime allocation) ----------------
__device__ float g_S2 [(size_t)Nn * Nn];                 // support2 = 2L^2 - I
__device__ float g_Wg [(size_t)Nn * KI * OG];            // per-node gate weights
__device__ float g_Wu [(size_t)Nn * KI * OU];            // per-node upd weights
__device__ float g_bg [(size_t)Nn * OG];
__device__ float g_bu [(size_t)Nn * OU];
__device__ float g_XG [(size_t)Bb * Nn * KI];            // [b][n][k*96+c] diffused features
__device__ float g_X0 [(size_t)Bb * Nn * OG];            // init_gconv out (gate 128 / upd 64)
__device__ float g_XG1[(size_t)Bb * Nn * 3 * OG];        // cheb-diffused x0 (gate 384 / upd 192)
__device__ float g_G0 [(size_t)Bb * Nn * OG];            // gconv0
__device__ float g_G1 [(size_t)Bb * Nn * OG];            // gconv1
__device__ float g_Rb [(size_t)Bb * Nn * DOUT];          // gate r
__device__ float g_Y0 [Bb * OG];
__device__ float g_Y1 [Bb * OG];
__device__ float g_s0 [Bb];
__device__ float g_s1 [Bb];
__device__ float g_iwTg[CIN * OG];
__device__ float g_gwTg[3 * OG * OG];
__device__ float g_iwTu[CIN * OU];
__device__ float g_gwTu[3 * OU * OU];

// ---------------- helpers ----------------
static __device__ __forceinline__ float lrelu(float v) {
    return v >= 0.0f ? v : 0.01f * v;
}
static __device__ __forceinline__ float sigmoidf(float v) {
    return 1.0f / (1.0f + expf(-v));
}

// ---------------- generic tiled SGEMM: C = alpha*A@B (+bias per col) (- I) ----------------
// A row-major [M,Kd] lda ; B row-major [Kd,N] ldb ; C row-major [M,N] ldc.
// blockIdx.z applies strideA/strideB/strideC (batched). Kd must be a multiple of 16,
// A/B base pointers and lds multiples of 4 floats (true for all uses here).
__global__ __launch_bounds__(256) void sgemm_kernel(
    const float* __restrict__ A, int lda, long strideA,
    const float* __restrict__ Bm, int ldb, long strideB,
    float* __restrict__ C, int ldc, long strideC,
    int M, int Ncols, int Kd,
    const float* __restrict__ bias, float alpha, int minusI)
{
    A  += (long)blockIdx.z * strideA;
    Bm += (long)blockIdx.z * strideB;
    C  += (long)blockIdx.z * strideC;

    __shared__ float As[16][68];   // padded: 2-way store conflicts max, aligned float4 reads
    __shared__ float Bs[16][64];

    const int tid  = threadIdx.x;
    const int trow = tid >> 4;      // 0..15
    const int tcol = tid & 15;      // 0..15
    const int row0 = blockIdx.y * 64 + trow * 4;
    const int col0 = blockIdx.x * 64 + tcol * 4;

    const int a_m  = tid >> 2;           // 0..63
    const int a_k4 = (tid & 3) * 4;      // 0,4,8,12
    const int b_k  = tid >> 4;           // 0..15
    const int b_n4 = (tid & 15) * 4;     // 0..60

    const int gm = blockIdx.y * 64 + a_m;
    const int gn = blockIdx.x * 64 + b_n4;

    float acc[4][4] = {};

    for (int k0 = 0; k0 < Kd; k0 += 16) {
        float4 av = make_float4(0.f, 0.f, 0.f, 0.f);
        if (gm < M) av = *(const float4*)(A + (long)gm * lda + k0 + a_k4);
        As[a_k4 + 0][a_m] = av.x;
        As[a_k4 + 1][a_m] = av.y;
        As[a_k4 + 2][a_m] = av.z;
        As[a_k4 + 3][a_m] = av.w;

        float4 bv = make_float4(0.f, 0.f, 0.f, 0.f);
        {
            const float* bp = Bm + (long)(k0 + b_k) * ldb;
            if (gn + 3 < Ncols) {
                bv = *(const float4*)(bp + gn);
            } else if (gn < Ncols) {
                bv.x = bp[gn];
                if (gn + 1 < Ncols) bv.y = bp[gn + 1];
                if (gn + 2 < Ncols) bv.z = bp[gn + 2];
            }
        }
        *(float4*)(&Bs[b_k][b_n4]) = bv;

        __syncthreads();

        #pragma unroll
        for (int k = 0; k < 16; k++) {
            float4 a4 = *(const float4*)(&As[k][trow * 4]);
            float4 b4 = *(const float4*)(&Bs[k][tcol * 4]);
            acc[0][0] += a4.x * b4.x; acc[0][1] += a4.x * b4.y; acc[0][2] += a4.x * b4.z; acc[0][3] += a4.x * b4.w;
            acc[1][0] += a4.y * b4.x; acc[1][1] += a4.y * b4.y; acc[1][2] += a4.y * b4.z; acc[1][3] += a4.y * b4.w;
            acc[2][0] += a4.z * b4.x; acc[2][1] += a4.z * b4.y; acc[2][2] += a4.z * b4.z; acc[2][3] += a4.z * b4.w;
            acc[3][0] += a4.w * b4.x; acc[3][1] += a4.w * b4.y; acc[3][2] += a4.w * b4.z; acc[3][3] += a4.w * b4.w;
        }
        __syncthreads();
    }

    #pragma unroll
    for (int i = 0; i < 4; i++) {
        int m = row0 + i;
        if (m >= M) continue;
        const long crow = (long)m * ldc;
        #pragma unroll
        for (int j = 0; j < 4; j++) {
            int nn = col0 + j;
            if (nn >= Ncols) continue;
            float v = acc[i][j] * alpha;
            if (bias) v += __ldg(&bias[nn]);
            if (minusI && m == nn) v -= 1.0f;
            C[crow + nn] = v;
        }
    }
}

// ---------------- per-node dynamic-weight contraction (grouped GEMM) ----------------
// out[b,n,o] = sum_{ki<288} XG[b,n,ki] * W[n,ki,o] + bias[n,o] ; one block per node.
template <int O>
__global__ __launch_bounds__(256) void pernode_gconv(
    const float* __restrict__ XG, const float* __restrict__ W,
    const float* __restrict__ bias, float* __restrict__ out)
{
    constexpr int TN = O / 16;      // 8 (gate) or 4 (upd)
    const int n   = blockIdx.x;
    const int tid = threadIdx.x;
    const int trow = tid >> 4;      // 0..15 -> 4 batch rows each
    const int tcol = tid & 15;      // 0..15 -> TN cols (stride 16)

    __shared__ float As[64][33];    // [b][k] chunk, padded
    __shared__ float Ws[32][O];

    const float* Wn = W + (long)n * KI * O;

    float acc[4][TN];
    #pragma unroll
    for (int i = 0; i < 4; i++)
        #pragma unroll
        for (int j = 0; j < TN; j++) acc[i][j] = 0.f;

    const int lb = tid >> 2;          // 0..63 batch row
    const int lk = (tid & 3) * 8;     // 0,8,16,24

    for (int k0 = 0; k0 < KI; k0 += 32) {
        const float* src = XG + ((long)lb * Nn + n) * KI + k0 + lk;
        float4 v0 = *(const float4*)(src);
        float4 v1 = *(const float4*)(src + 4);
        As[lb][lk + 0] = v0.x; As[lb][lk + 1] = v0.y; As[lb][lk + 2] = v0.z; As[lb][lk + 3] = v0.w;
        As[lb][lk + 4] = v1.x; As[lb][lk + 5] = v1.y; As[lb][lk + 6] = v1.z; As[lb][lk + 7] = v1.w;

        const float* wsrc = Wn + (long)k0 * O;
        #pragma unroll
        for (int i = tid * 4; i < 32 * O; i += 1024)
            *(float4*)(&Ws[0][0] + i) = *(const float4*)(wsrc + i);

        __syncthreads();

        #pragma unroll
        for (int k = 0; k < 32; k++) {
            float a0 = As[trow * 4 + 0][k];
            float a1 = As[trow * 4 + 1][k];
            float a2 = As[trow * 4 + 2][k];
            float a3 = As[trow * 4 + 3][k];
            #pragma unroll
            for (int j = 0; j < TN; j++) {
                float w = Ws[k][tcol + 16 * j];
                acc[0][j] += a0 * w;
                acc[1][j] += a1 * w;
                acc[2][j] += a2 * w;
                acc[3][j] += a3 * w;
            }
        }
        __syncthreads();
    }

    #pragma unroll
    for (int i = 0; i < 4; i++) {
        int b = trow * 4 + i;
        #pragma unroll
        for (int j = 0; j < TN; j++) {
            int o = tcol + 16 * j;
            out[((long)b * Nn + n) * O + o] = acc[i][j] + bias[(long)n * O + o];
        }
    }
}

// ---------------- small kernels ----------------
// out[n, j] = sum_d emb[n,d] * pool[d, j]   (grid.y = n)
__global__ void emb_matmul(const float* __restrict__ emb, const float* __restrict__ pool,
                           float* __restrict__ out, int C)
{
    int nrow = blockIdx.y;
    float e[EDm];
    #pragma unroll
    for (int d = 0; d < EDm; d++) e[d] = emb[nrow * EDm + d];
    for (int j = blockIdx.x * blockDim.x + threadIdx.x; j < C; j += gridDim.x * blockDim.x) {
        float acc = 0.f;
        #pragma unroll
        for (int d = 0; d < EDm; d++) acc += e[d] * pool[(long)d * C + j];
        out[(long)nrow * C + j] = acc;
    }
}

// out[c*R + r] = in[r*C + c]
__global__ void transpose_rc(const float* __restrict__ in, float* __restrict__ out, int R, int C)
{
    int idx = blockIdx.x * blockDim.x + threadIdx.x;
    if (idx < R * C) {
        int r = idx / C, c = idx % C;
        out[(long)c * R + r] = in[idx];
    }
}

// XG k=0 slot <- concat(x, state)
__global__ void build_xg0(const float* __restrict__ x, const float* __restrict__ st,
                          float* __restrict__ XG)
{
    long idx = (long)blockIdx.x * blockDim.x + threadIdx.x;
    if (idx >= (long)Bb * Nn * CIN) return;
    int c = (int)(idx % CIN);
    long bn = idx / CIN;
    float v = (c < DIN) ? x[bn * DIN + c] : st[bn * DOUT + (c - DIN)];
    XG[bn * KI + c] = v;
}

// Y[b,c] = mean_n lrelu(G[b,n,c]) ; blockDim = C, grid = B
__global__ void colmean_lrelu(const float* __restrict__ G, float* __restrict__ Y, int C)
{
    int b = blockIdx.x, c = threadIdx.x;
    const float* p = G + (long)b * Nn * C + c;
    float a0 = 0.f, a1 = 0.f, a2 = 0.f, a3 = 0.f;
    for (int n = 0; n < Nn; n += 4) {
        a0 += lrelu(p[(long)(n + 0) * C]);
        a1 += lrelu(p[(long)(n + 1) * C]);
        a2 += lrelu(p[(long)(n + 2) * C]);
        a3 += lrelu(p[(long)(n + 3) * C]);
    }
    Y[b * C + c] = (a0 + a1 + a2 + a3) * (1.0f / (float)Nn);
}

// s[b] = sigmoid( sum_j relu(Y[b,:] . w1[j,:]) * w2[j] )  ; grid = B, 32 threads
__global__ void att_scalar(const float* __restrict__ Y, const float* __restrict__ w1,
                           const float* __restrict__ w2, float* __restrict__ s, int C, int H)
{
    int b = blockIdx.x, j = threadIdx.x;
    float h = 0.f;
    if (j < H) {
        float acc = 0.f;
        for (int c = 0; c < C; c++) acc += Y[b * C + c] * w1[j * C + c];
        h = fmaxf(acc, 0.f) * w2[j];
    }
    #pragma unroll
    for (int off = 16; off; off >>= 1) h += __shfl_down_sync(0xffffffffu, h, off);
    if (j == 0) s[b] = sigmoidf(h);
}

// z_r = sigmoid(lrelu(G0)*s0 + lrelu(G1)*s1); store r; candidate -> XG k0 slot
__global__ void gate_combine(const float* __restrict__ G0, const float* __restrict__ G1,
                             const float* __restrict__ s0, const float* __restrict__ s1,
                             const float* __restrict__ x, const float* __restrict__ st,
                             float* __restrict__ XG, float* __restrict__ Rb)
{
    long idx = (long)blockIdx.x * blockDim.x + threadIdx.x;
    if (idx >= (long)Bb * Nn * DOUT) return;
    int o = (int)(idx % DOUT);
    long bn = idx / DOUT;
    int b = (int)(bn >> 10);
    float a0 = s0[b], a1 = s1[b];
    float zi = lrelu(G0[bn * OG + o]) * a0 + lrelu(G1[bn * OG + o]) * a1;
    float ri = lrelu(G0[bn * OG + DOUT + o]) * a0 + lrelu(G1[bn * OG + DOUT + o]) * a1;
    float z = sigmoidf(zi);
    float r = sigmoidf(ri);
    Rb[idx] = r;
    XG[bn * KI + DIN + o] = z * st[idx];
    if (o < DIN) XG[bn * KI + o] = x[bn * DIN + o];
}

// h = r*state + (1-r)*tanh(lrelu(G0u)*t0 + lrelu(G1u)*t1)
__global__ void final_combine(const float* __restrict__ G0u, const float* __restrict__ G1u,
                              const float* __restrict__ t0, const float* __restrict__ t1,
                              const float* __restrict__ Rb, const float* __restrict__ st,
                              float* __restrict__ out)
{
    long idx = (long)blockIdx.x * blockDim.x + threadIdx.x;
    if (idx >= (long)Bb * Nn * DOUT) return;
    long bn = idx / DOUT;
    int b = (int)(bn >> 10);
    float hc = tanhf(lrelu(G0u[idx]) * t0[b] + lrelu(G1u[idx]) * t1[b]);
    float r = Rb[idx];
    out[idx] = r * st[idx] + (1.0f - r) * hc;
}

// ---------------- host side ----------------
static inline void sgemm(const float* A, int lda, long sA,
                         const float* Bm, int ldb, long sB,
                         float* Cm, int ldc, long sC,
                         int M, int Ncols, int Kd, int batch,
                         const float* bias, float alpha, int minusI)
{
    dim3 grid((Ncols + 63) / 64, (M + 63) / 64, batch);
    sgemm_kernel<<<grid, 256>>>(A, lda, sA, Bm, ldb, sB, Cm, ldc, sC,
                                M, Ncols, Kd, bias, alpha, minusI);
}

extern "C" void kernel_launch(void* const* d_in, const int* in_sizes, int n_in,
                              void* d_out, int out_size)
{
    const float* x     = (const float*)d_in[0];
    const float* state = (const float*)d_in[1];
    const float* emb   = (const float*)d_in[2];
    const float* Lm    = (const float*)d_in[3];
    const float* cheb  = (const float*)d_in[4];
    const float* gwpool = (const float*)d_in[5];
    const float* gbpool = (const float*)d_in[6];
    const float* giw    = (const float*)d_in[7];
    const float* gib    = (const float*)d_in[8];
    const float* ggw    = (const float*)d_in[9];
    const float* ggb    = (const float*)d_in[10];
    const float* ga1w1  = (const float*)d_in[11];
    const float* ga1w2  = (const float*)d_in[12];
    const float* ga2w1  = (const float*)d_in[13];
    const float* ga2w2  = (const float*)d_in[14];
    const float* uwpool = (const float*)d_in[15];
    const float* ubpool = (const float*)d_in[16];
    const float* uiw    = (const float*)d_in[17];
    const float* uib    = (const float*)d_in[18];
    const float* ugw    = (const float*)d_in[19];
    const float* ugb    = (const float*)d_in[20];
    const float* ua1w1  = (const float*)d_in[21];
    const float* ua1w2  = (const float*)d_in[22];
    const float* ua2w1  = (const float*)d_in[23];
    const float* ua2w2  = (const float*)d_in[24];
    float* out = (float*)d_out;

    float *S2, *Wg, *Wu, *bg, *bu, *XG, *X0, *XG1, *G0, *G1, *Rb, *Y0, *Y1, *s0, *s1;
    float *iwTg, *gwTg, *iwTu, *gwTu;
    cudaGetSymbolAddress((void**)&S2,  g_S2);
    cudaGetSymbolAddress((void**)&Wg,  g_Wg);
    cudaGetSymbolAddress((void**)&Wu,  g_Wu);
    cudaGetSymbolAddress((void**)&bg,  g_bg);
    cudaGetSymbolAddress((void**)&bu,  g_bu);
    cudaGetSymbolAddress((void**)&XG,  g_XG);
    cudaGetSymbolAddress((void**)&X0,  g_X0);
    cudaGetSymbolAddress((void**)&XG1, g_XG1);
    cudaGetSymbolAddress((void**)&G0,  g_G0);
    cudaGetSymbolAddress((void**)&G1,  g_G1);
    cudaGetSymbolAddress((void**)&Rb,  g_Rb);
    cudaGetSymbolAddress((void**)&Y0,  g_Y0);
    cudaGetSymbolAddress((void**)&Y1,  g_Y1);
    cudaGetSymbolAddress((void**)&s0,  g_s0);
    cudaGetSymbolAddress((void**)&s1,  g_s1);
    cudaGetSymbolAddress((void**)&iwTg, g_iwTg);
    cudaGetSymbolAddress((void**)&gwTg, g_gwTg);
    cudaGetSymbolAddress((void**)&iwTu, g_iwTu);
    cudaGetSymbolAddress((void**)&gwTu, g_gwTu);

    const long sXG  = (long)Nn * KI;

    // ---- per-node weights / biases from node embeddings ----
    emb_matmul<<<dim3((KI * OG + 255) / 256, Nn), 256>>>(emb, gwpool, Wg, KI * OG);
    emb_matmul<<<dim3(1, Nn), 256>>>(emb, gbpool, bg, OG);
    emb_matmul<<<dim3((KI * OU + 255) / 256, Nn), 256>>>(emb, uwpool, Wu, KI * OU);
    emb_matmul<<<dim3(1, Nn), 256>>>(emb, ubpool, bu, OU);

    // ---- transpose small dense weights ----
    transpose_rc<<<(OG * CIN + 255) / 256, 256>>>(giw, iwTg, OG, CIN);
    transpose_rc<<<(OG * 3 * OG + 255) / 256, 256>>>(ggw, gwTg, OG, 3 * OG);
    transpose_rc<<<(OU * CIN + 255) / 256, 256>>>(uiw, iwTu, OU, CIN);
    transpose_rc<<<(OU * 3 * OU + 255) / 256, 256>>>(ugw, gwTu, OU, 3 * OU);

    // ---- S2 = 2*L@L - I ----
    sgemm(Lm, Nn, 0, Lm, Nn, 0, S2, Nn, 0, Nn, Nn, Nn, 1, nullptr, 2.0f, 1);

    // ================= GATE =================
    build_xg0<<<((long)Bb * Nn * CIN + 255) / 256, 256>>>(x, state, XG);
    // k=1: L @ U ; k=2: S2 @ U  (batched over b)
    sgemm(Lm, Nn, 0, XG, KI, sXG, XG + CIN,     KI, sXG, Nn, CIN, Nn, Bb, nullptr, 1.0f, 0);
    sgemm(S2, Nn, 0, XG, KI, sXG, XG + 2 * CIN, KI, sXG, Nn, CIN, Nn, Bb, nullptr, 1.0f, 0);
    // per-node contraction
    pernode_gconv<OG><<<Nn, 256>>>(XG, Wg, bg, G0);
    // x0 = U @ iwT + ib   (A rows = XG rows, first 96 cols)
    sgemm(XG, KI, 0, iwTg, OG, 0, X0, OG, 0, Bb * Nn, OG, CIN, 1, gib, 1.0f, 0);
    // cheb diffusion of x0
    for (int k = 0; k < KSUP; k++)
        sgemm(cheb + (long)k * Nn * Nn, Nn, 0, X0, OG, (long)Nn * OG,
              XG1 + k * OG, 3 * OG, (long)Nn * 3 * OG, Nn, OG, Nn, Bb, nullptr, 1.0f, 0);
    // gconv1 = XG1 @ gwT + gb
    sgemm(XG1, 3 * OG, 0, gwTg, OG, 0, G1, OG, 0, Bb * Nn, OG, 3 * OG, 1, ggb, 1.0f, 0);
    // attention scalars + combine
    colmean_lrelu<<<Bb, OG>>>(G0, Y0, OG);
    colmean_lrelu<<<Bb, OG>>>(G1, Y1, OG);
    att_scalar<<<Bb, 32>>>(Y0, ga1w1, ga1w2, s0, OG, OG / 16);
    att_scalar<<<Bb, 32>>>(Y1, ga2w1, ga2w2, s1, OG, OG / 16);
    gate_combine<<<((long)Bb * Nn * DOUT + 255) / 256, 256>>>(G0, G1, s0, s1, x, state, XG, Rb);

    // ================= UPDATE =================
    sgemm(Lm, Nn, 0, XG, KI, sXG, XG + CIN,     KI, sXG, Nn, CIN, Nn, Bb, nullptr, 1.0f, 0);
    sgemm(S2, Nn, 0, XG, KI, sXG, XG + 2 * CIN, KI, sXG, Nn, CIN, Nn, Bb, nullptr, 1.0f, 0);
    pernode_gconv<OU><<<Nn, 256>>>(XG, Wu, bu, G0);
    sgemm(XG, KI, 0, iwTu, OU, 0, X0, OU, 0, Bb * Nn, OU, CIN, 1, uib, 1.0f, 0);
    for (int k = 0; k < KSUP; k++)
        sgemm(cheb + (long)k * Nn * Nn, Nn, 0, X0, OU, (long)Nn * OU,
              XG1 + k * OU, 3 * OU, (long)Nn * 3 * OU, Nn, OU, Nn, Bb, nullptr, 1.0f, 0);
    sgemm(XG1, 3 * OU, 0, gwTu, OU, 0, G1, OU, 0, Bb * Nn, OU, 3 * OU, 1, ugb, 1.0f, 0);
    colmean_lrelu<<<Bb, OU>>>(G0, Y0, OU);
    colmean_lrelu<<<Bb, OU>>>(G1, Y1, OU);
    att_scalar<<<Bb, 32>>>(Y0, ua1w1, ua1w2, s0, OU, OU / 16);
    att_scalar<<<Bb, 32>>>(Y1, ua2w1, ua2w2, s1, OU, OU / 16);
    final_combine<<<((long)Bb * Nn * DOUT + 255) / 256, 256>>>(G0, G1, s0, s1, Rb, state, out);
}

// round 2
// speedup vs baseline: 1.6004x; 1.6004x over previous
#include <cuda_runtime.h>
#include <math.h>

// ---------------- problem constants ----------------
#define Bb   64
#define Nn   1024
#define DIN  32
#define DOUT 64
#define CIN  96        // DIN + DOUT
#define KSUP 3
#define EDm  16
#define OG   128       // gate output (2*DOUT)
#define OU   64        // update output
#define KI   288       // KSUP * CIN

// ---------------- scratch (device globals; no runtime allocation) ----------------
__device__ float g_S2 [(size_t)Nn * Nn];                 // support2 = 2L^2 - I
__device__ float g_Wg [(size_t)Nn * KI * OG];            // per-node gate weights
__device__ float g_Wu [(size_t)Nn * KI * OU];            // per-node upd weights
__device__ float g_bg [(size_t)Nn * OG];
__device__ float g_bu [(size_t)Nn * OU];
__device__ float g_XG [(size_t)Bb * Nn * KI];            // [b][n][k*96+c] diffused features
__device__ float g_X0 [(size_t)Bb * Nn * OG];            // init_gconv out (gate 128 / upd 64)
__device__ float g_XG1[(size_t)Bb * Nn * 3 * OG];        // cheb-diffused x0 (gate 384 / upd 192)
__device__ float g_G0 [(size_t)Bb * Nn * OG];            // gconv0
__device__ float g_G1 [(size_t)Bb * Nn * OG];            // gconv1
__device__ float g_Rb [(size_t)Bb * Nn * DOUT];          // gate r
__device__ float g_Y0 [Bb * OG];
__device__ float g_Y1 [Bb * OG];
__device__ float g_s0 [Bb];
__device__ float g_s1 [Bb];
__device__ float g_iwTg[CIN * OG];
__device__ float g_gwTg[3 * OG * OG];
__device__ float g_iwTu[CIN * OU];
__device__ float g_gwTu[3 * OU * OU];

// ---------------- helpers ----------------
static __device__ __forceinline__ float lrelu(float v) {
    return v >= 0.0f ? v : 0.01f * v;
}
static __device__ __forceinline__ float sigmoidf(float v) {
    return 1.0f / (1.0f + expf(-v));
}

// ---------------- generic tiled SGEMM: C = alpha*A@B (+bias per col) (- I) ----------------
// A row-major [M,Kd] lda ; B row-major [Kd,N] ldb ; C row-major [M,N] ldc.
// blockIdx.z applies strideA/strideB/strideC (batched). Kd must be a multiple of 16,
// A/B base pointers and lds multiples of 4 floats (true for all uses here).
__global__ __launch_bounds__(256) void sgemm_kernel(
    const float* __restrict__ A, int lda, long strideA,
    const float* __restrict__ Bm, int ldb, long strideB,
    float* __restrict__ C, int ldc, long strideC,
    int M, int Ncols, int Kd,
    const float* __restrict__ bias, float alpha, int minusI)
{
    A  += (long)blockIdx.z * strideA;
    Bm += (long)blockIdx.z * strideB;
    C  += (long)blockIdx.z * strideC;

    __shared__ float As[16][68];   // padded: 2-way store conflicts max, aligned float4 reads
    __shared__ float Bs[16][64];

    const int tid  = threadIdx.x;
    const int trow = tid >> 4;      // 0..15
    const int tcol = tid & 15;      // 0..15
    const int row0 = blockIdx.y * 64 + trow * 4;
    const int col0 = blockIdx.x * 64 + tcol * 4;

    const int a_m  = tid >> 2;           // 0..63
    const int a_k4 = (tid & 3) * 4;      // 0,4,8,12
    const int b_k  = tid >> 4;           // 0..15
    const int b_n4 = (tid & 15) * 4;     // 0..60

    const int gm = blockIdx.y * 64 + a_m;
    const int gn = blockIdx.x * 64 + b_n4;

    float acc[4][4] = {};

    for (int k0 = 0; k0 < Kd; k0 += 16) {
        float4 av = make_float4(0.f, 0.f, 0.f, 0.f);
        if (gm < M) av = *(const float4*)(A + (long)gm * lda + k0 + a_k4);
        As[a_k4 + 0][a_m] = av.x;
        As[a_k4 + 1][a_m] = av.y;
        As[a_k4 + 2][a_m] = av.z;
        As[a_k4 + 3][a_m] = av.w;

        float4 bv = make_float4(0.f, 0.f, 0.f, 0.f);
        {
            const float* bp = Bm + (long)(k0 + b_k) * ldb;
            if (gn + 3 < Ncols) {
                bv = *(const float4*)(bp + gn);
            } else if (gn < Ncols) {
                bv.x = bp[gn];
                if (gn + 1 < Ncols) bv.y = bp[gn + 1];
                if (gn + 2 < Ncols) bv.z = bp[gn + 2];
            }
        }
        *(float4*)(&Bs[b_k][b_n4]) = bv;

        __syncthreads();

        #pragma unroll
        for (int k = 0; k < 16; k++) {
            float4 a4 = *(const float4*)(&As[k][trow * 4]);
            float4 b4 = *(const float4*)(&Bs[k][tcol * 4]);
            acc[0][0] += a4.x * b4.x; acc[0][1] += a4.x * b4.y; acc[0][2] += a4.x * b4.z; acc[0][3] += a4.x * b4.w;
            acc[1][0] += a4.y * b4.x; acc[1][1] += a4.y * b4.y; acc[1][2] += a4.y * b4.z; acc[1][3] += a4.y * b4.w;
            acc[2][0] += a4.z * b4.x; acc[2][1] += a4.z * b4.y; acc[2][2] += a4.z * b4.z; acc[2][3] += a4.z * b4.w;
            acc[3][0] += a4.w * b4.x; acc[3][1] += a4.w * b4.y; acc[3][2] += a4.w * b4.z; acc[3][3] += a4.w * b4.w;
        }
        __syncthreads();
    }

    #pragma unroll
    for (int i = 0; i < 4; i++) {
        int m = row0 + i;
        if (m >= M) continue;
        const long crow = (long)m * ldc;
        #pragma unroll
        for (int j = 0; j < 4; j++) {
            int nn = col0 + j;
            if (nn >= Ncols) continue;
            float v = acc[i][j] * alpha;
            if (bias) v += __ldg(&bias[nn]);
            if (minusI && m == nn) v -= 1.0f;
            C[crow + nn] = v;
        }
    }
}

// ---------------- per-node dynamic-weight contraction (grouped GEMM) ----------------
// out[b,n,o] = sum_{ki<288} XG[b,n,ki] * W[n,ki,o] + bias[n,o] ; one block per node.
template <int O>
__global__ __launch_bounds__(256) void pernode_gconv(
    const float* __restrict__ XG, const float* __restrict__ W,
    const float* __restrict__ bias, float* __restrict__ out)
{
    constexpr int TN = O / 16;      // 8 (gate) or 4 (upd)
    const int n   = blockIdx.x;
    const int tid = threadIdx.x;
    const int trow = tid >> 4;      // 0..15 -> 4 batch rows each
    const int tcol = tid & 15;      // 0..15 -> TN cols (stride 16)

    __shared__ float As[64][33];    // [b][k] chunk, padded
    __shared__ float Ws[32][O];

    const float* Wn = W + (long)n * KI * O;

    float acc[4][TN];
    #pragma unroll
    for (int i = 0; i < 4; i++)
        #pragma unroll
        for (int j = 0; j < TN; j++) acc[i][j] = 0.f;

    const int lb = tid >> 2;          // 0..63 batch row
    const int lk = (tid & 3) * 8;     // 0,8,16,24

    for (int k0 = 0; k0 < KI; k0 += 32) {
        const float* src = XG + ((long)lb * Nn + n) * KI + k0 + lk;
        float4 v0 = *(const float4*)(src);
        float4 v1 = *(const float4*)(src + 4);
        As[lb][lk + 0] = v0.x; As[lb][lk + 1] = v0.y; As[lb][lk + 2] = v0.z; As[lb][lk + 3] = v0.w;
        As[lb][lk + 4] = v1.x; As[lb][lk + 5] = v1.y; As[lb][lk + 6] = v1.z; As[lb][lk + 7] = v1.w;

        const float* wsrc = Wn + (long)k0 * O;
        #pragma unroll
        for (int i = tid * 4; i < 32 * O; i += 1024)
            *(float4*)(&Ws[0][0] + i) = *(const float4*)(wsrc + i);

        __syncthreads();

        #pragma unroll
        for (int k = 0; k < 32; k++) {
            float a0 = As[trow * 4 + 0][k];
            float a1 = As[trow * 4 + 1][k];
            float a2 = As[trow * 4 + 2][k];
            float a3 = As[trow * 4 + 3][k];
            #pragma unroll
            for (int j = 0; j < TN; j++) {
                float w = Ws[k][tcol + 16 * j];
                acc[0][j] += a0 * w;
                acc[1][j] += a1 * w;
                acc[2][j] += a2 * w;
                acc[3][j] += a3 * w;
            }
        }
        __syncthreads();
    }

    #pragma unroll
    for (int i = 0; i < 4; i++) {
        int b = trow * 4 + i;
        #pragma unroll
        for (int j = 0; j < TN; j++) {
            int o = tcol + 16 * j;
            out[((long)b * Nn + n) * O + o] = acc[i][j] + bias[(long)n * O + o];
        }
    }
}

// ---------------- small kernels ----------------
// out[n, j] = sum_d emb[n,d] * pool[d, j]   (grid.y = n)
__global__ void emb_matmul(const float* __restrict__ emb, const float* __restrict__ pool,
                           float* __restrict__ out, int C)
{
    int nrow = blockIdx.y;
    float e[EDm];
    #pragma unroll
    for (int d = 0; d < EDm; d++) e[d] = emb[nrow * EDm + d];
    for (int j = blockIdx.x * blockDim.x + threadIdx.x; j < C; j += gridDim.x * blockDim.x) {
        float acc = 0.f;
        #pragma unroll
        for (int d = 0; d < EDm; d++) acc += e[d] * pool[(long)d * C + j];
        out[(long)nrow * C + j] = acc;
    }
}

// out[c*R + r] = in[r*C + c]
__global__ void transpose_rc(const float* __restrict__ in, float* __restrict__ out, int R, int C)
{
    int idx = blockIdx.x * blockDim.x + threadIdx.x;
    if (idx < R * C) {
        int r = idx / C, c = idx % C;
        out[(long)c * R + r] = in[idx];
    }
}

// XG k=0 slot <- concat(x, state)
__global__ void build_xg0(const float* __restrict__ x, const float* __restrict__ st,
                          float* __restrict__ XG)
{
    long idx = (long)blockIdx.x * blockDim.x + threadIdx.x;
    if (idx >= (long)Bb * Nn * CIN) return;
    int c = (int)(idx % CIN);
    long bn = idx / CIN;
    float v = (c < DIN) ? x[bn * DIN + c] : st[bn * DOUT + (c - DIN)];
    XG[bn * KI + c] = v;
}

// Y[b,c] = mean_n lrelu(G[b,n,c]) ; blockDim = C, grid = B
__global__ void colmean_lrelu(const float* __restrict__ G, float* __restrict__ Y, int C)
{
    int b = blockIdx.x, c = threadIdx.x;
    const float* p = G + (long)b * Nn * C + c;
    float a0 = 0.f, a1 = 0.f, a2 = 0.f, a3 = 0.f;
    for (int n = 0; n < Nn; n += 4) {
        a0 += lrelu(p[(long)(n + 0) * C]);
        a1 += lrelu(p[(long)(n + 1) * C]);
        a2 += lrelu(p[(long)(n + 2) * C]);
        a3 += lrelu(p[(long)(n + 3) * C]);
    }
    Y[b * C + c] = (a0 + a1 + a2 + a3) * (1.0f / (float)Nn);
}

// s[b] = sigmoid( sum_j relu(Y[b,:] . w1[j,:]) * w2[j] )  ; grid = B, 32 threads
__global__ void att_scalar(const float* __restrict__ Y, const float* __restrict__ w1,
                           const float* __restrict__ w2, float* __restrict__ s, int C, int H)
{
    int b = blockIdx.x, j = threadIdx.x;
    float h = 0.f;
    if (j < H) {
        float acc = 0.f;
        for (int c = 0; c < C; c++) acc += Y[b * C + c] * w1[j * C + c];
        h = fmaxf(acc, 0.f) * w2[j];
    }
    #pragma unroll
    for (int off = 16; off; off >>= 1) h += __shfl_down_sync(0xffffffffu, h, off);
    if (j == 0) s[b] = sigmoidf(h);
}

// z_r = sigmoid(lrelu(G0)*s0 + lrelu(G1)*s1); store r; candidate -> XG k0 slot
__global__ void gate_combine(const float* __restrict__ G0, const float* __restrict__ G1,
                             const float* __restrict__ s0, const float* __restrict__ s1,
                             const float* __restrict__ x, const float* __restrict__ st,
                             float* __restrict__ XG, float* __restrict__ Rb)
{
    long idx = (long)blockIdx.x * blockDim.x + threadIdx.x;
    if (idx >= (long)Bb * Nn * DOUT) return;
    int o = (int)(idx % DOUT);
    long bn = idx / DOUT;
    int b = (int)(bn >> 10);
    float a0 = s0[b], a1 = s1[b];
    float zi = lrelu(G0[bn * OG + o]) * a0 + lrelu(G1[bn * OG + o]) * a1;
    float ri = lrelu(G0[bn * OG + DOUT + o]) * a0 + lrelu(G1[bn * OG + DOUT + o]) * a1;
    float z = sigmoidf(zi);
    float r = sigmoidf(ri);
    Rb[idx] = r;
    XG[bn * KI + DIN + o] = z * st[idx];
    if (o < DIN) XG[bn * KI + o] = x[bn * DIN + o];
}

// h = r*state + (1-r)*tanh(lrelu(G0u)*t0 + lrelu(G1u)*t1)
__global__ void final_combine(const float* __restrict__ G0u, const float* __restrict__ G1u,
                              const float* __restrict__ t0, const float* __restrict__ t1,
                              const float* __restrict__ Rb, const float* __restrict__ st,
                              float* __restrict__ out)
{
    long idx = (long)blockIdx.x * blockDim.x + threadIdx.x;
    if (idx >= (long)Bb * Nn * DOUT) return;
    long bn = idx / DOUT;
    int b = (int)(bn >> 10);
    float hc = tanhf(lrelu(G0u[idx]) * t0[b] + lrelu(G1u[idx]) * t1[b]);
    float r = Rb[idx];
    out[idx] = r * st[idx] + (1.0f - r) * hc;
}

// ---------------- host side ----------------
static inline void sgemm(const float* A, int lda, long sA,
                         const float* Bm, int ldb, long sB,
                         float* Cm, int ldc, long sC,
                         int M, int Ncols, int Kd, int batch,
                         const float* bias, float alpha, int minusI)
{
    dim3 grid((Ncols + 63) / 64, (M + 63) / 64, batch);
    sgemm_kernel<<<grid, 256>>>(A, lda, sA, Bm, ldb, sB, Cm, ldc, sC,
                                M, Ncols, Kd, bias, alpha, minusI);
}

extern "C" void kernel_launch(void* const* d_in, const int* in_sizes, int n_in,
                              void* d_out, int out_size)
{
    const float* x     = (const float*)d_in[0];
    const float* state = (const float*)d_in[1];
    const float* emb   = (const float*)d_in[2];
    const float* Lm    = (const float*)d_in[3];
    const float* cheb  = (const float*)d_in[4];
    const float* gwpool = (const float*)d_in[5];
    const float* gbpool = (const float*)d_in[6];
    const float* giw    = (const float*)d_in[7];
    const float* gib    = (const float*)d_in[8];
    const float* ggw    = (const float*)d_in[9];
    const float* ggb    = (const float*)d_in[10];
    const float* ga1w1  = (const float*)d_in[11];
    const float* ga1w2  = (const float*)d_in[12];
    const float* ga2w1  = (const float*)d_in[13];
    const float* ga2w2  = (const float*)d_in[14];
    const float* uwpool = (const float*)d_in[15];
    const float* ubpool = (const float*)d_in[16];
    const float* uiw    = (const float*)d_in[17];
    const float* uib    = (const float*)d_in[18];
    const float* ugw    = (const float*)d_in[19];
    const float* ugb    = (const float*)d_in[20];
    const float* ua1w1  = (const float*)d_in[21];
    const float* ua1w2  = (const float*)d_in[22];
    const float* ua2w1  = (const float*)d_in[23];
    const float* ua2w2  = (const float*)d_in[24];
    float* out = (float*)d_out;

    float *S2, *Wg, *Wu, *bg, *bu, *XG, *X0, *XG1, *G0, *G1, *Rb, *Y0, *Y1, *s0, *s1;
    float *iwTg, *gwTg, *iwTu, *gwTu;
    cudaGetSymbolAddress((void**)&S2,  g_S2);
    cudaGetSymbolAddress((void**)&Wg,  g_Wg);
    cudaGetSymbolAddress((void**)&Wu,  g_Wu);
    cudaGetSymbolAddress((void**)&bg,  g_bg);
    cudaGetSymbolAddress((void**)&bu,  g_bu);
    cudaGetSymbolAddress((void**)&XG,  g_XG);
    cudaGetSymbolAddress((void**)&X0,  g_X0);
    cudaGetSymbolAddress((void**)&XG1, g_XG1);
    cudaGetSymbolAddress((void**)&G0,  g_G0);
    cudaGetSymbolAddress((void**)&G1,  g_G1);
    cudaGetSymbolAddress((void**)&Rb,  g_Rb);
    cudaGetSymbolAddress((void**)&Y0,  g_Y0);
    cudaGetSymbolAddress((void**)&Y1,  g_Y1);
    cudaGetSymbolAddress((void**)&s0,  g_s0);
    cudaGetSymbolAddress((void**)&s1,  g_s1);
    cudaGetSymbolAddress((void**)&iwTg, g_iwTg);
    cudaGetSymbolAddress((void**)&gwTg, g_gwTg);
    cudaGetSymbolAddress((void**)&iwTu, g_iwTu);
    cudaGetSymbolAddress((void**)&gwTu, g_gwTu);

    const long sXG  = (long)Nn * KI;

    // ---- per-node weights / biases from node embeddings ----
    emb_matmul<<<dim3((KI * OG + 255) / 256, Nn), 256>>>(emb, gwpool, Wg, KI * OG);
    emb_matmul<<<dim3(1, Nn), 256>>>(emb, gbpool, bg, OG);
    emb_matmul<<<dim3((KI * OU + 255) / 256, Nn), 256>>>(emb, uwpool, Wu, KI * OU);
    emb_matmul<<<dim3(1, Nn), 256>>>(emb, ubpool, bu, OU);

    // ---- transpose small dense weights ----
    transpose_rc<<<(OG * CIN + 255) / 256, 256>>>(giw, iwTg, OG, CIN);
    transpose_rc<<<(OG * 3 * OG + 255) / 256, 256>>>(ggw, gwTg, OG, 3 * OG);
    transpose_rc<<<(OU * CIN + 255) / 256, 256>>>(uiw, iwTu, OU, CIN);
    transpose_rc<<<(OU * 3 * OU + 255) / 256, 256>>>(ugw, gwTu, OU, 3 * OU);

    // ---- S2 = 2*L@L - I ----
    sgemm(Lm, Nn, 0, Lm, Nn, 0, S2, Nn, 0, Nn, Nn, Nn, 1, nullptr, 2.0f, 1);

    // ================= GATE =================
    build_xg0<<<((long)Bb * Nn * CIN + 255) / 256, 256>>>(x, state, XG);
    // k=1: L @ U ; k=2: S2 @ U  (batched over b)
    sgemm(Lm, Nn, 0, XG, KI, sXG, XG + CIN,     KI, sXG, Nn, CIN, Nn, Bb, nullptr, 1.0f, 0);
    sgemm(S2, Nn, 0, XG, KI, sXG, XG + 2 * CIN, KI, sXG, Nn, CIN, Nn, Bb, nullptr, 1.0f, 0);
    // per-node contraction
    pernode_gconv<OG><<<Nn, 256>>>(XG, Wg, bg, G0);
    // x0 = U @ iwT + ib   (A rows = XG rows, first 96 cols)
    sgemm(XG, KI, 0, iwTg, OG, 0, X0, OG, 0, Bb * Nn, OG, CIN, 1, gib, 1.0f, 0);
    // cheb diffusion of x0
    for (int k = 0; k < KSUP; k++)
        sgemm(cheb + (long)k * Nn * Nn, Nn, 0, X0, OG, (long)Nn * OG,
              XG1 + k * OG, 3 * OG, (long)Nn * 3 * OG, Nn, OG, Nn, Bb, nullptr, 1.0f, 0);
    // gconv1 = XG1 @ gwT + gb
    sgemm(XG1, 3 * OG, 0, gwTg, OG, 0, G1, OG, 0, Bb * Nn, OG, 3 * OG, 1, ggb, 1.0f, 0);
    // attention scalars + combine
    colmean_lrelu<<<Bb, OG>>>(G0, Y0, OG);
    colmean_lrelu<<<Bb, OG>>>(G1, Y1, OG);
    att_scalar<<<Bb, 32>>>(Y0, ga1w1, ga1w2, s0, OG, OG / 16);
    att_scalar<<<Bb, 32>>>(Y1, ga2w1, ga2w2, s1, OG, OG / 16);
    gate_combine<<<((long)Bb * Nn * DOUT + 255) / 256, 256>>>(G0, G1, s0, s1, x, state, XG, Rb);

    // ================= UPDATE =================
    sgemm(Lm, Nn, 0, XG, KI, sXG, XG + CIN,     KI, sXG, Nn, CIN, Nn, Bb, nullptr, 1.0f, 0);
    sgemm(S2, Nn, 0, XG, KI, sXG, XG + 2 * CIN, KI, sXG, Nn, CIN, Nn, Bb, nullptr, 1.0f, 0);
    pernode_gconv<OU><<<Nn, 256>>>(XG, Wu, bu, G0);
    sgemm(XG, KI, 0, iwTu, OU, 0, X0, OU, 0, Bb * Nn, OU, CIN, 1, uib, 1.0f, 0);
    for (int k = 0; k < KSUP; k++)
        sgemm(cheb + (long)k * Nn * Nn, Nn, 0, X0, OU, (long)Nn * OU,
              XG1 + k * OU, 3 * OU, (long)Nn * 3 * OU, Nn, OU, Nn, Bb, nullptr, 1.0f, 0);
    sgemm(XG1, 3 * OU, 0, gwTu, OU, 0, G1, OU, 0, Bb * Nn, OU, 3 * OU, 1, ugb, 1.0f, 0);
    colmean_lrelu<<<Bb, OU>>>(G0, Y0, OU);
    colmean_lrelu<<<Bb, OU>>>(G1, Y1, OU);
    att_scalar<<<Bb, 32>>>(Y0, ua1w1, ua1w2, s0, OU, OU / 16);
    att_scalar<<<Bb, 32>>>(Y1, ua2w1, ua2w2, s1, OU, OU / 16);
    final_combine<<<((long)Bb * Nn * DOUT + 255) / 256, 256>>>(G0, G1, s0, s1, Rb, state, out);
}

// round 4
// speedup vs baseline: 1.7805x; 1.1125x over previous
#include <cuda_runtime.h>
#include <math.h>
#include <stdint.h>

#define Bb   64
#define Nn   1024
#define DIN  32
#define DOUT 64
#define CIN  96
#define KSUP 3
#define EDm  16
#define OG   128
#define OU   64
#define KI   288

__device__ float g_S2 [(size_t)Nn * Nn];
__device__ float g_Lt [(size_t)Nn * Nn];
__device__ float g_Wg [(size_t)Nn * KI * OG];
__device__ float g_Wu [(size_t)Nn * KI * OU];
__device__ float g_bg [(size_t)Nn * OG];
__device__ float g_bu [(size_t)Nn * OU];
__device__ float g_XG [(size_t)Bb * Nn * KI];
__device__ float g_Ucm[(size_t)Bb * CIN * Nn];
__device__ float g_X0 [(size_t)Bb * Nn * OG];
__device__ float g_X0T[(size_t)Bb * OG * Nn];
__device__ float g_XG1[(size_t)Bb * Nn * 3 * OG];
__device__ float g_G0 [(size_t)Bb * Nn * OG];
__device__ float g_G1 [(size_t)Bb * Nn * OG];
__device__ float g_Rb [(size_t)Bb * Nn * DOUT];
__device__ float g_Y0 [Bb * OG];
__device__ float g_Y1 [Bb * OG];
__device__ float g_s0 [Bb];
__device__ float g_s1 [Bb];

static __device__ __forceinline__ float to_tf32(float v) {
    uint32_t u; asm("cvt.rna.tf32.f32 %0, %1;" : "=r"(u) : "f"(v));
    return __uint_as_float(u);
}
static __device__ __forceinline__ void mma8(float* d, const uint32_t* a,
                                            uint32_t b0, uint32_t b1) {
    asm volatile(
        "mma.sync.aligned.m16n8k8.row.col.f32.tf32.tf32.f32 "
        "{%0,%1,%2,%3}, {%4,%5,%6,%7}, {%8,%9}, {%0,%1,%2,%3};"
        : "+f"(d[0]), "+f"(d[1]), "+f"(d[2]), "+f"(d[3])
        : "r"(a[0]), "r"(a[1]), "r"(a[2]), "r"(a[3]), "r"(b0), "r"(b1));
}

#define SA 20   // smem row stride (floats): conflict-free fragment reads

// ---------- tf32 3x-split GEMM: D[m,n] = alpha*sum_k A[m,k]*B[n,k] (+bias[n]) (-I) ----
// M%128==0 (grid.y), N = NT*grid.x, K%16==0, batch = grid.z.
template <int NT>
__global__ __launch_bounds__(256, 1) void mma_gemm(
    const float* __restrict__ A, int lda, long sA,
    const float* __restrict__ Bm, int ldb, long sB,
    float* __restrict__ C, int ldc, long sC,
    int K, const float* __restrict__ bias, float alpha, int minusI)
{
    constexpr int NTILES = NT / 16;     // n-tiles of 8 per warp (warp covers NT/2)
    __shared__ float Ah[128 * SA], Al[128 * SA];
    __shared__ float Bh[NT * SA],  Bl[NT * SA];

    A += (long)blockIdx.z * sA; Bm += (long)blockIdx.z * sB; C += (long)blockIdx.z * sC;
    const int m0 = blockIdx.y * 128, n0 = blockIdx.x * NT;
    const int tid = threadIdx.x, wid = tid >> 5, lid = tid & 31;
    const int g = lid >> 2, t = lid & 3;
    const int wm = (wid & 3) * 32, wn = (wid >> 2) * (NT / 2);

    const float* Ag = A + (long)m0 * lda;
    const float* Bg = Bm + (long)n0 * ldb;

    float acc[2][NTILES][4];
    #pragma unroll
    for (int i = 0; i < 2; i++)
        #pragma unroll
        for (int j = 0; j < NTILES; j++)
            #pragma unroll
            for (int q = 0; q < 4; q++) acc[i][j][q] = 0.f;

    for (int k0 = 0; k0 < K; k0 += 16) {
        // ---- stage A (128x16) as hi/lo float2 ----
        #pragma unroll
        for (int i = 0; i < 4; i++) {
            int f = i * 256 + tid;
            int row = f >> 3, c2 = (f & 7) * 2;
            float2 v = *(const float2*)(Ag + (long)row * lda + k0 + c2);
            float hx = to_tf32(v.x), hy = to_tf32(v.y);
            int off = row * SA + c2;
            *(float2*)(Ah + off) = make_float2(hx, hy);
            *(float2*)(Al + off) = make_float2(to_tf32(v.x - hx), to_tf32(v.y - hy));
        }
        // ---- stage B (NTx16) ----
        #pragma unroll
        for (int i = 0; i < NT / 32; i++) {
            int f = i * 256 + tid;
            int row = f >> 3, c2 = (f & 7) * 2;
            float2 v = *(const float2*)(Bg + (long)row * ldb + k0 + c2);
            float hx = to_tf32(v.x), hy = to_tf32(v.y);
            int off = row * SA + c2;
            *(float2*)(Bh + off) = make_float2(hx, hy);
            *(float2*)(Bl + off) = make_float2(to_tf32(v.x - hx), to_tf32(v.y - hy));
        }
        __syncthreads();

        #pragma unroll
        for (int kk = 0; kk < 2; kk++) {
            const int kc = kk * 8 + t;
            uint32_t ah[2][4], al[2][4];
            #pragma unroll
            for (int mt = 0; mt < 2; mt++) {
                int r = (wm + mt * 16 + g) * SA + kc;
                ah[mt][0] = __float_as_uint(Ah[r]);
                ah[mt][1] = __float_as_uint(Ah[r + 8 * SA]);
                ah[mt][2] = __float_as_uint(Ah[r + 4]);
                ah[mt][3] = __float_as_uint(Ah[r + 8 * SA + 4]);
                al[mt][0] = __float_as_uint(Al[r]);
                al[mt][1] = __float_as_uint(Al[r + 8 * SA]);
                al[mt][2] = __float_as_uint(Al[r + 4]);
                al[mt][3] = __float_as_uint(Al[r + 8 * SA + 4]);
            }
            #pragma unroll
            for (int nt = 0; nt < NTILES; nt++) {
                int boff = (wn + nt * 8 + g) * SA + kc;
                uint32_t bh0 = __float_as_uint(Bh[boff]);
                uint32_t bh1 = __float_as_uint(Bh[boff + 4]);
                uint32_t bl0 = __float_as_uint(Bl[boff]);
                uint32_t bl1 = __float_as_uint(Bl[boff + 4]);
                #pragma unroll
                for (int mt = 0; mt < 2; mt++) {
                    mma8(acc[mt][nt], ah[mt], bh0, bh1);
                    mma8(acc[mt][nt], al[mt], bh0, bh1);
                    mma8(acc[mt][nt], ah[mt], bl0, bl1);
                }
            }
        }
        __syncthreads();
    }

    // ---- epilogue ----
    #pragma unroll
    for (int mt = 0; mt < 2; mt++) {
        int r0 = m0 + wm + mt * 16 + g;
        #pragma unroll
        for (int nt = 0; nt < NTILES; nt++) {
            int col = n0 + wn + nt * 8 + t * 2;
            float b0 = 0.f, b1 = 0.f;
            if (bias) { b0 = __ldg(&bias[col]); b1 = __ldg(&bias[col + 1]); }
            float d0 = acc[mt][nt][0] * alpha + b0;
            float d1 = acc[mt][nt][1] * alpha + b1;
            float d2 = acc[mt][nt][2] * alpha + b0;
            float d3 = acc[mt][nt][3] * alpha + b1;
            if (minusI) {
                if (r0 == col)         d0 -= 1.0f;
                if (r0 == col + 1)     d1 -= 1.0f;
                if (r0 + 8 == col)     d2 -= 1.0f;
                if (r0 + 8 == col + 1) d3 -= 1.0f;
            }
            *(float2*)(C + (long)r0 * ldc + col)       = make_float2(d0, d1);
            *(float2*)(C + (long)(r0 + 8) * ldc + col) = make_float2(d2, d3);
        }
    }
}

// ---------- per-node dynamic-weight contraction (SIMT fp32, proven) ----------
template <int O>
__global__ __launch_bounds__(256) void pernode_gconv(
    const float* __restrict__ XG, const float* __restrict__ W,
    const float* __restrict__ bias, float* __restrict__ out)
{
    constexpr int TN = O / 16;
    const int n = blockIdx.x, tid = threadIdx.x;
    const int trow = tid >> 4, tcol = tid & 15;
    __shared__ float As[64][33];
    __shared__ float Ws[32][O];
    const float* Wn = W + (long)n * KI * O;
    float acc[4][TN];
    #pragma unroll
    for (int i = 0; i < 4; i++)
        #pragma unroll
        for (int j = 0; j < TN; j++) acc[i][j] = 0.f;
    const int lb = tid >> 2, lk = (tid & 3) * 8;
    for (int k0 = 0; k0 < KI; k0 += 32) {
        const float* src = XG + ((long)lb * Nn + n) * KI + k0 + lk;
        float4 v0 = *(const float4*)(src);
        float4 v1 = *(const float4*)(src + 4);
        As[lb][lk + 0] = v0.x; As[lb][lk + 1] = v0.y; As[lb][lk + 2] = v0.z; As[lb][lk + 3] = v0.w;
        As[lb][lk + 4] = v1.x; As[lb][lk + 5] = v1.y; As[lb][lk + 6] = v1.z; As[lb][lk + 7] = v1.w;
        const float* wsrc = Wn + (long)k0 * O;
        #pragma unroll
        for (int i = tid * 4; i < 32 * O; i += 1024)
            *(float4*)(&Ws[0][0] + i) = *(const float4*)(wsrc + i);
        __syncthreads();
        #pragma unroll
        for (int k = 0; k < 32; k++) {
            float a0 = As[trow * 4 + 0][k], a1 = As[trow * 4 + 1][k];
            float a2 = As[trow * 4 + 2][k], a3 = As[trow * 4 + 3][k];
            #pragma unroll
            for (int j = 0; j < TN; j++) {
                float w = Ws[k][tcol + 16 * j];
                acc[0][j] += a0 * w; acc[1][j] += a1 * w;
                acc[2][j] += a2 * w; acc[3][j] += a3 * w;
            }
        }
        __syncthreads();
    }
    #pragma unroll
    for (int i = 0; i < 4; i++) {
        int b = trow * 4 + i;
        #pragma unroll
        for (int j = 0; j < TN; j++) {
            int o = tcol + 16 * j;
            out[((long)b * Nn + n) * O + o] = acc[i][j] + bias[(long)n * O + o];
        }
    }
}

// ---------- small kernels ----------
static __device__ __forceinline__ float lrelu(float v) { return v >= 0.0f ? v : 0.01f * v; }
static __device__ __forceinline__ float sigmoidf(float v) { return 1.0f / (1.0f + expf(-v)); }

__global__ void emb_matmul(const float* __restrict__ emb, const float* __restrict__ pool,
                           float* __restrict__ out, int C)
{
    int nrow = blockIdx.y;
    float e[EDm];
    #pragma unroll
    for (int d = 0; d < EDm; d++) e[d] = emb[nrow * EDm + d];
    for (int j = blockIdx.x * blockDim.x + threadIdx.x; j < C; j += gridDim.x * blockDim.x) {
        float acc = 0.f;
        #pragma unroll
        for (int d = 0; d < EDm; d++) acc += e[d] * pool[(long)d * C + j];
        out[(long)nrow * C + j] = acc;
    }
}

__global__ void transpose_batched(const float* __restrict__ in, long s_in, int ld_in,
                                  float* __restrict__ out, long s_out, int ld_out,
                                  int R, int Cc)
{
    __shared__ float tsm[32][33];
    in  += (long)blockIdx.z * s_in;
    out += (long)blockIdx.z * s_out;
    int r0 = blockIdx.x * 32, c0 = blockIdx.y * 32;
    int c = c0 + threadIdx.x;
    #pragma unroll
    for (int i = 0; i < 32; i += 8) {
        int rr = r0 + threadIdx.y + i;
        if (rr < R && c < Cc) tsm[threadIdx.y + i][threadIdx.x] = in[(long)rr * ld_in + c];
    }
    __syncthreads();
    int rr = r0 + threadIdx.x;
    #pragma unroll
    for (int i = 0; i < 32; i += 8) {
        int cc = c0 + threadIdx.y + i;
        if (cc < Cc && rr < R) out[(long)cc * ld_out + rr] = tsm[threadIdx.x][threadIdx.y + i];
    }
}

__global__ void build_xg0(const float* __restrict__ x, const float* __restrict__ st,
                          float* __restrict__ XG)
{
    long idx = (long)blockIdx.x * blockDim.x + threadIdx.x;
    if (idx >= (long)Bb * Nn * CIN) return;
    int c = (int)(idx % CIN);
    long bn = idx / CIN;
    XG[bn * KI + c] = (c < DIN) ? x[bn * DIN + c] : st[bn * DOUT + (c - DIN)];
}

__global__ void colmean_lrelu(const float* __restrict__ G, float* __restrict__ Y, int C)
{
    int b = blockIdx.x, c = threadIdx.x;
    const float* p = G + (long)b * Nn * C + c;
    float a0 = 0.f, a1 = 0.f, a2 = 0.f, a3 = 0.f;
    for (int n = 0; n < Nn; n += 4) {
        a0 += lrelu(p[(long)(n + 0) * C]); a1 += lrelu(p[(long)(n + 1) * C]);
        a2 += lrelu(p[(long)(n + 2) * C]); a3 += lrelu(p[(long)(n + 3) * C]);
    }
    Y[b * C + c] = (a0 + a1 + a2 + a3) * (1.0f / (float)Nn);
}

__global__ void att_scalar(const float* __restrict__ Y, const float* __restrict__ w1,
                           const float* __restrict__ w2, float* __restrict__ s, int C, int H)
{
    int b = blockIdx.x, j = threadIdx.x;
    float h = 0.f;
    if (j < H) {
        float acc = 0.f;
        for (int c = 0; c < C; c++) acc += Y[b * C + c] * w1[j * C + c];
        h = fmaxf(acc, 0.f) * w2[j];
    }
    #pragma unroll
    for (int off = 16; off; off >>= 1) h += __shfl_down_sync(0xffffffffu, h, off);
    if (j == 0) s[b] = sigmoidf(h);
}

__global__ void gate_combine(const float* __restrict__ G0, const float* __restrict__ G1,
                             const float* __restrict__ s0, const float* __restrict__ s1,
                             const float* __restrict__ x, const float* __restrict__ st,
                             float* __restrict__ XG, float* __restrict__ Rb)
{
    long idx = (long)blockIdx.x * blockDim.x + threadIdx.x;
    if (idx >= (long)Bb * Nn * DOUT) return;
    int o = (int)(idx % DOUT);
    long bn = idx / DOUT;
    int b = (int)(bn >> 10);
    float a0 = s0[b], a1 = s1[b];
    float zi = lrelu(G0[bn * OG + o]) * a0 + lrelu(G1[bn * OG + o]) * a1;
    float ri = lrelu(G0[bn * OG + DOUT + o]) * a0 + lrelu(G1[bn * OG + DOUT + o]) * a1;
    float r = sigmoidf(ri);
    Rb[idx] = r;
    XG[bn * KI + DIN + o] = sigmoidf(zi) * st[idx];
    if (o < DIN) XG[bn * KI + o] = x[bn * DIN + o];
}

__global__ void final_combine(const float* __restrict__ G0u, const float* __restrict__ G1u,
                              const float* __restrict__ t0, const float* __restrict__ t1,
                              const float* __restrict__ Rb, const float* __restrict__ st,
                              float* __restrict__ out)
{
    long idx = (long)blockIdx.x * blockDim.x + threadIdx.x;
    if (idx >= (long)Bb * Nn * DOUT) return;
    long bn = idx / DOUT;
    int b = (int)(bn >> 10);
    float hc = tanhf(lrelu(G0u[idx]) * t0[b] + lrelu(G1u[idx]) * t1[b]);
    float r = Rb[idx];
    out[idx] = r * st[idx] + (1.0f - r) * hc;
}

// ---------- host ----------
static inline void tc(const float* A, int lda, long sA, const float* Bm, int ldb, long sB,
                      float* C, int ldc, long sC, int M, int N, int NT, int K, int batch,
                      const float* bias, float alpha, int mI)
{
    dim3 grid(N / NT, M / 128, batch);
    switch (NT) {
    case 128: mma_gemm<128><<<grid, 256>>>(A, lda, sA, Bm, ldb, sB, C, ldc, sC, K, bias, alpha, mI); break;
    case  96: mma_gemm< 96><<<grid, 256>>>(A, lda, sA, Bm, ldb, sB, C, ldc, sC, K, bias, alpha, mI); break;
    default:  mma_gemm< 64><<<grid, 256>>>(A, lda, sA, Bm, ldb, sB, C, ldc, sC, K, bias, alpha, mI); break;
    }
}

extern "C" void kernel_launch(void* const* d_in, const int* in_sizes, int n_in,
                              void* d_out, int out_size)
{
    const float* x     = (const float*)d_in[0];
    const float* state = (const float*)d_in[1];
    const float* emb   = (const float*)d_in[2];
    const float* Lm    = (const float*)d_in[3];
    const float* cheb  = (const float*)d_in[4];
    const float* gwpool = (const float*)d_in[5];
    const float* gbpool = (const float*)d_in[6];
    const float* giw = (const float*)d_in[7];
    const float* gib = (const float*)d_in[8];
    const float* ggw = (const float*)d_in[9];
    const float* ggb = (const float*)d_in[10];
    const float* ga1w1 = (const float*)d_in[11];
    const float* ga1w2 = (const float*)d_in[12];
    const float* ga2w1 = (const float*)d_in[13];
    const float* ga2w2 = (const float*)d_in[14];
    const float* uwpool = (const float*)d_in[15];
    const float* ubpool = (const float*)d_in[16];
    const float* uiw = (const float*)d_in[17];
    const float* uib = (const float*)d_in[18];
    const float* ugw = (const float*)d_in[19];
    const float* ugb = (const float*)d_in[20];
    const float* ua1w1 = (const float*)d_in[21];
    const float* ua1w2 = (const float*)d_in[22];
    const float* ua2w1 = (const float*)d_in[23];
    const float* ua2w2 = (const float*)d_in[24];
    float* out = (float*)d_out;

    float *S2, *Lt, *Wg, *Wu, *bg, *bu, *XG, *Ucm, *X0, *X0T, *XG1;
    float *G0, *G1, *Rb, *Y0, *Y1, *s0, *s1;
    cudaGetSymbolAddress((void**)&S2,  g_S2);
    cudaGetSymbolAddress((void**)&Lt,  g_Lt);
    cudaGetSymbolAddress((void**)&Wg,  g_Wg);
    cudaGetSymbolAddress((void**)&Wu,  g_Wu);
    cudaGetSymbolAddress((void**)&bg,  g_bg);
    cudaGetSymbolAddress((void**)&bu,  g_bu);
    cudaGetSymbolAddress((void**)&XG,  g_XG);
    cudaGetSymbolAddress((void**)&Ucm, g_Ucm);
    cudaGetSymbolAddress((void**)&X0,  g_X0);
    cudaGetSymbolAddress((void**)&X0T, g_X0T);
    cudaGetSymbolAddress((void**)&XG1, g_XG1);
    cudaGetSymbolAddress((void**)&G0,  g_G0);
    cudaGetSymbolAddress((void**)&G1,  g_G1);
    cudaGetSymbolAddress((void**)&Rb,  g_Rb);
    cudaGetSymbolAddress((void**)&Y0,  g_Y0);
    cudaGetSymbolAddress((void**)&Y1,  g_Y1);
    cudaGetSymbolAddress((void**)&s0,  g_s0);
    cudaGetSymbolAddress((void**)&s1,  g_s1);

    const long sXG = (long)Nn * KI;
    dim3 tb(32, 8);

    // per-node weights / biases
    emb_matmul<<<dim3(144, Nn), 256>>>(emb, gwpool, Wg, KI * OG);
    emb_matmul<<<dim3(72, Nn), 256>>>(emb, uwpool, Wu, KI * OU);
    emb_matmul<<<dim3(1, Nn), 256>>>(emb, gbpool, bg, OG);
    emb_matmul<<<dim3(1, Nn), 256>>>(emb, ubpool, bu, OU);

    // S2 = 2*L@L - I  (B operand = L^T, K-major)
    transpose_batched<<<dim3(32, 32, 1), tb>>>(Lm, 0, Nn, Lt, 0, Nn, Nn, Nn);
    tc(Lm, Nn, 0, Lt, Nn, 0, S2, Nn, 0, Nn, Nn, 128, Nn, 1, nullptr, 2.0f, 1);

    // ===== GATE =====
    build_xg0<<<((long)Bb * Nn * CIN + 255) / 256, 256>>>(x, state, XG);
    transpose_batched<<<dim3(32, 3, Bb), tb>>>(XG, sXG, KI, Ucm, (long)CIN * Nn, Nn, Nn, CIN);
    tc(Lm, Nn, 0, Ucm, Nn, (long)CIN * Nn, XG + CIN,     KI, sXG, Nn, CIN, 96, Nn, Bb, nullptr, 1.0f, 0);
    tc(S2, Nn, 0, Ucm, Nn, (long)CIN * Nn, XG + 2 * CIN, KI, sXG, Nn, CIN, 96, Nn, Bb, nullptr, 1.0f, 0);
    pernode_gconv<OG><<<Nn, 256>>>(XG, Wg, bg, G0);
    tc(XG, KI, 0, giw, CIN, 0, X0, OG, 0, Bb * Nn, OG, 128, CIN, 1, gib, 1.0f, 0);
    transpose_batched<<<dim3(32, 4, Bb), tb>>>(X0, (long)Nn * OG, OG, X0T, (long)OG * Nn, Nn, Nn, OG);
    for (int k = 0; k < KSUP; k++)
        tc(cheb + (long)k * Nn * Nn, Nn, 0, X0T, Nn, (long)OG * Nn,
           XG1 + k * OG, 3 * OG, (long)Nn * 3 * OG, Nn, OG, 128, Nn, Bb, nullptr, 1.0f, 0);
    tc(XG1, 3 * OG, 0, ggw, 3 * OG, 0, G1, OG, 0, Bb * Nn, OG, 128, 3 * OG, 1, ggb, 1.0f, 0);
    colmean_lrelu<<<Bb, OG>>>(G0, Y0, OG);
    colmean_lrelu<<<Bb, OG>>>(G1, Y1, OG);
    att_scalar<<<Bb, 32>>>(Y0, ga1w1, ga1w2, s0, OG, OG / 16);
    att_scalar<<<Bb, 32>>>(Y1, ga2w1, ga2w2, s1, OG, OG / 16);
    gate_combine<<<((long)Bb * Nn * DOUT + 255) / 256, 256>>>(G0, G1, s0, s1, x, state, XG, Rb);

    // ===== UPDATE =====
    transpose_batched<<<dim3(32, 3, Bb), tb>>>(XG, sXG, KI, Ucm, (long)CIN * Nn, Nn, Nn, CIN);
    tc(Lm, Nn, 0, Ucm, Nn, (long)CIN * Nn, XG + CIN,     KI, sXG, Nn, CIN, 96, Nn, Bb, nullptr, 1.0f, 0);
    tc(S2, Nn, 0, Ucm, Nn, (long)CIN * Nn, XG + 2 * CIN, KI, sXG, Nn, CIN, 96, Nn, Bb, nullptr, 1.0f, 0);
    pernode_gconv<OU><<<Nn, 256>>>(XG, Wu, bu, G0);
    tc(XG, KI, 0, uiw, CIN, 0, X0, OU, 0, Bb * Nn, OU, 64, CIN, 1, uib, 1.0f, 0);
    transpose_batched<<<dim3(32, 2, Bb), tb>>>(X0, (long)Nn * OU, OU, X0T, (long)OU * Nn, Nn, Nn, OU);
    for (int k = 0; k < KSUP; k++)
        tc(cheb + (long)k * Nn * Nn, Nn, 0, X0T, Nn, (long)OU * Nn,
           XG1 + k * OU, 3 * OU, (long)Nn * 3 * OU, Nn, OU, 64, Nn, Bb, nullptr, 1.0f, 0);
    tc(XG1, 3 * OU, 0, ugw, 3 * OU, 0, G1, OU, 0, Bb * Nn, OU, 64, 3 * OU, 1, ugb, 1.0f, 0);
    colmean_lrelu<<<Bb, OU>>>(G0, Y0, OU);
    colmean_lrelu<<<Bb, OU>>>(G1, Y1, OU);
    att_scalar<<<Bb, 32>>>(Y0, ua1w1, ua1w2, s0, OU, OU / 16);
    att_scalar<<<Bb, 32>>>(Y1, ua2w1, ua2w2, s1, OU, OU / 16);
    final_combine<<<((long)Bb * Nn * DOUT + 255) / 256, 256>>>(G0, G1, s0, s1, Rb, state, out);
}

// round 6
// speedup vs baseline: 3.6746x; 2.0638x over previous
#include <cuda_runtime.h>
#include <cuda_bf16.h>
#include <math.h>
#include <stdint.h>

#define Bb   64
#define Nn   1024
#define DIN  32
#define DOUT 64
#define CIN  96
#define KSUP 3
#define EDm  16
#define OG   128
#define OU   64
#define KI   288

__device__ float g_S2 [(size_t)Nn * Nn];
__device__ float g_Lt [(size_t)Nn * Nn];
__device__ float g_Wg [(size_t)Nn * KI * OG];
__device__ float g_Wu [(size_t)Nn * KI * OU];
__device__ float g_bg [(size_t)Nn * OG];
__device__ float g_bu [(size_t)Nn * OU];
__device__ float g_XG [(size_t)Bb * Nn * KI];
__device__ float g_Ucm[(size_t)Bb * CIN * Nn];
__device__ float g_X0 [(size_t)Bb * Nn * OG];
__device__ float g_X0T[(size_t)Bb * OG * Nn];
__device__ float g_XG1[(size_t)Bb * Nn * 3 * OG];
__device__ float g_G0 [(size_t)Bb * Nn * OG];
__device__ float g_G1 [(size_t)Bb * Nn * OG];
__device__ float g_Rb [(size_t)Bb * Nn * DOUT];
__device__ float g_Y0 [Bb * OG];
__device__ float g_Y1 [Bb * OG];
__device__ float g_s0 [Bb];
__device__ float g_s1 [Bb];

// ---------- mma helpers ----------
static __device__ __forceinline__ void mma16(float* d, const uint32_t* a,
                                             uint32_t b0, uint32_t b1) {
    asm volatile(
        "mma.sync.aligned.m16n8k16.row.col.f32.bf16.bf16.f32 "
        "{%0,%1,%2,%3}, {%4,%5,%6,%7}, {%8,%9}, {%0,%1,%2,%3};"
        : "+f"(d[0]), "+f"(d[1]), "+f"(d[2]), "+f"(d[3])
        : "r"(a[0]), "r"(a[1]), "r"(a[2]), "r"(a[3]), "r"(b0), "r"(b1));
}
static __device__ __forceinline__ uint32_t packbf(float x, float y) {
    __nv_bfloat162 h = __floats2bfloat162_rn(x, y);
    return *reinterpret_cast<uint32_t*>(&h);
}
// float4 -> hi pair (2 u32) + lo pair (2 u32)
static __device__ __forceinline__ void split4(float4 v, uint2& hi, uint2& lo) {
    __nv_bfloat16 hx = __float2bfloat16_rn(v.x);
    __nv_bfloat16 hy = __float2bfloat16_rn(v.y);
    __nv_bfloat16 hz = __float2bfloat16_rn(v.z);
    __nv_bfloat16 hw = __float2bfloat16_rn(v.w);
    __nv_bfloat162 p0; p0.x = hx; p0.y = hy;
    __nv_bfloat162 p1; p1.x = hz; p1.y = hw;
    hi.x = *reinterpret_cast<uint32_t*>(&p0);
    hi.y = *reinterpret_cast<uint32_t*>(&p1);
    lo.x = packbf(v.x - __bfloat162float(hx), v.y - __bfloat162float(hy));
    lo.y = packbf(v.z - __bfloat162float(hz), v.w - __bfloat162float(hw));
}

#define RSTR 20   // smem row stride in u32 (conflict-free fragment reads, u64-aligned)

// ---------- bf16x3 GEMM: D[m,n] = alpha*sum_k A[m,k]*B[n,k] (+bias[n]) (-I) ----------
// M%128==0 (grid.y), N = NT*grid.x, K%32==0, batch = grid.z. Double-buffered K=32 chunks.
template <int NT>
__global__ __launch_bounds__(256, 1) void mma_gemm(
    const float* __restrict__ A, int lda, long sA,
    const float* __restrict__ Bm, int ldb, long sB,
    float* __restrict__ C, int ldc, long sC,
    int K, const float* __restrict__ bias, float alpha, int minusI)
{
    constexpr int NTILES = NT / 16;          // n8-tiles per warp (warp covers NT/2)
    constexpr int NB = NT / 32;              // B float4-iterations per thread
    constexpr int AROWS_U32 = 128 * RSTR;
    constexpr int BROWS_U32 = NT * RSTR;
    constexpr int STG = 2 * AROWS_U32 + 2 * BROWS_U32;   // u32 per stage

    extern __shared__ uint32_t dsm[];

    A += (long)blockIdx.z * sA; Bm += (long)blockIdx.z * sB; C += (long)blockIdx.z * sC;
    const int m0 = blockIdx.y * 128, n0 = blockIdx.x * NT;
    const int tid = threadIdx.x, wid = tid >> 5, lid = tid & 31;
    const int g = lid >> 2, t = lid & 3;
    const int wm = (wid & 3) * 32, wn = (wid >> 2) * (NT / 2);

    const float* Ag = A + (long)m0 * lda;
    const float* Bg = Bm + (long)n0 * ldb;

    float acc[2][NTILES][4];
    #pragma unroll
    for (int i = 0; i < 2; i++)
        #pragma unroll
        for (int j = 0; j < NTILES; j++)
            #pragma unroll
            for (int q = 0; q < 4; q++) acc[i][j][q] = 0.f;

    const int nch = K >> 5;
    float4 pA[4], pB[NB];

    // prologue: chunk 0
    #pragma unroll
    for (int i = 0; i < 4; i++) {
        int f = i * 256 + tid;
        pA[i] = *(const float4*)(Ag + (long)(f >> 3) * lda + ((f & 7) << 2));
    }
    #pragma unroll
    for (int i = 0; i < NB; i++) {
        int f = i * 256 + tid;
        pB[i] = *(const float4*)(Bg + (long)(f >> 3) * ldb + ((f & 7) << 2));
    }
    {
        uint32_t* Ah = dsm;                 uint32_t* Al = dsm + AROWS_U32;
        uint32_t* Bh = dsm + 2 * AROWS_U32; uint32_t* Bl = Bh + BROWS_U32;
        #pragma unroll
        for (int i = 0; i < 4; i++) {
            int f = i * 256 + tid, row = f >> 3, q = f & 7;
            uint2 hi, lo; split4(pA[i], hi, lo);
            *(uint2*)(Ah + row * RSTR + 2 * q) = hi;
            *(uint2*)(Al + row * RSTR + 2 * q) = lo;
        }
        #pragma unroll
        for (int i = 0; i < NB; i++) {
            int f = i * 256 + tid, row = f >> 3, q = f & 7;
            uint2 hi, lo; split4(pB[i], hi, lo);
            *(uint2*)(Bh + row * RSTR + 2 * q) = hi;
            *(uint2*)(Bl + row * RSTR + 2 * q) = lo;
        }
    }
    __syncthreads();

    for (int c = 0; c < nch; c++) {
        // prefetch next chunk to regs
        if (c + 1 < nch) {
            const int k0 = (c + 1) << 5;
            #pragma unroll
            for (int i = 0; i < 4; i++) {
                int f = i * 256 + tid;
                pA[i] = *(const float4*)(Ag + (long)(f >> 3) * lda + k0 + ((f & 7) << 2));
            }
            #pragma unroll
            for (int i = 0; i < NB; i++) {
                int f = i * 256 + tid;
                pB[i] = *(const float4*)(Bg + (long)(f >> 3) * ldb + k0 + ((f & 7) << 2));
            }
        }

        // MMA on current stage
        {
            const uint32_t* base = dsm + (c & 1) * STG;
            const uint32_t* Ah = base;                 const uint32_t* Al = base + AROWS_U32;
            const uint32_t* Bh = base + 2 * AROWS_U32; const uint32_t* Bl = Bh + BROWS_U32;
            #pragma unroll
            for (int s = 0; s < 2; s++) {
                uint32_t ah[2][4], al[2][4];
                #pragma unroll
                for (int mt = 0; mt < 2; mt++) {
                    int r = (wm + mt * 16 + g) * RSTR + s * 8 + t;
                    ah[mt][0] = Ah[r];               ah[mt][1] = Ah[r + 8 * RSTR];
                    ah[mt][2] = Ah[r + 4];           ah[mt][3] = Ah[r + 8 * RSTR + 4];
                    al[mt][0] = Al[r];               al[mt][1] = Al[r + 8 * RSTR];
                    al[mt][2] = Al[r + 4];           al[mt][3] = Al[r + 8 * RSTR + 4];
                }
                #pragma unroll
                for (int nt = 0; nt < NTILES; nt++) {
                    int bo = (wn + nt * 8 + g) * RSTR + s * 8 + t;
                    uint32_t bh0 = Bh[bo], bh1 = Bh[bo + 4];
                    uint32_t bl0 = Bl[bo], bl1 = Bl[bo + 4];
                    #pragma unroll
                    for (int mt = 0; mt < 2; mt++) {
                        mma16(acc[mt][nt], ah[mt], bh0, bh1);
                        mma16(acc[mt][nt], al[mt], bh0, bh1);
                        mma16(acc[mt][nt], ah[mt], bl0, bl1);
                    }
                }
            }
        }

        // store next chunk to alternate stage
        if (c + 1 < nch) {
            uint32_t* base = dsm + ((c + 1) & 1) * STG;
            uint32_t* Ah = base;                 uint32_t* Al = base + AROWS_U32;
            uint32_t* Bh = base + 2 * AROWS_U32; uint32_t* Bl = Bh + BROWS_U32;
            #pragma unroll
            for (int i = 0; i < 4; i++) {
                int f = i * 256 + tid, row = f >> 3, q = f & 7;
                uint2 hi, lo; split4(pA[i], hi, lo);
                *(uint2*)(Ah + row * RSTR + 2 * q) = hi;
                *(uint2*)(Al + row * RSTR + 2 * q) = lo;
            }
            #pragma unroll
            for (int i = 0; i < NB; i++) {
                int f = i * 256 + tid, row = f >> 3, q = f & 7;
                uint2 hi, lo; split4(pB[i], hi, lo);
                *(uint2*)(Bh + row * RSTR + 2 * q) = hi;
                *(uint2*)(Bl + row * RSTR + 2 * q) = lo;
            }
            __syncthreads();
        }
    }

    // ---- epilogue ----
    #pragma unroll
    for (int mt = 0; mt < 2; mt++) {
        int r0 = m0 + wm + mt * 16 + g;
        #pragma unroll
        for (int nt = 0; nt < NTILES; nt++) {
            int col = n0 + wn + nt * 8 + t * 2;
            float b0 = 0.f, b1 = 0.f;
            if (bias) { b0 = __ldg(&bias[col]); b1 = __ldg(&bias[col + 1]); }
            float d0 = acc[mt][nt][0] * alpha + b0;
            float d1 = acc[mt][nt][1] * alpha + b1;
            float d2 = acc[mt][nt][2] * alpha + b0;
            float d3 = acc[mt][nt][3] * alpha + b1;
            if (minusI) {
                if (r0 == col)         d0 -= 1.0f;
                if (r0 == col + 1)     d1 -= 1.0f;
                if (r0 + 8 == col)     d2 -= 1.0f;
                if (r0 + 8 == col + 1) d3 -= 1.0f;
            }
            *(float2*)(C + (long)r0 * ldc + col)       = make_float2(d0, d1);
            *(float2*)(C + (long)(r0 + 8) * ldc + col) = make_float2(d2, d3);
        }
    }
}

// ---------- per-node dynamic-weight contraction (SIMT fp32, proven) ----------
template <int O>
__global__ __launch_bounds__(256) void pernode_gconv(
    const float* __restrict__ XG, const float* __restrict__ W,
    const float* __restrict__ bias, float* __restrict__ out)
{
    constexpr int TN = O / 16;
    const int n = blockIdx.x, tid = threadIdx.x;
    const int trow = tid >> 4, tcol = tid & 15;
    __shared__ float As[64][33];
    __shared__ float Ws[32][O];
    const float* Wn = W + (long)n * KI * O;
    float acc[4][TN];
    #pragma unroll
    for (int i = 0; i < 4; i++)
        #pragma unroll
        for (int j = 0; j < TN; j++) acc[i][j] = 0.f;
    const int lb = tid >> 2, lk = (tid & 3) * 8;
    for (int k0 = 0; k0 < KI; k0 += 32) {
        const float* src = XG + ((long)lb * Nn + n) * KI + k0 + lk;
        float4 v0 = *(const float4*)(src);
        float4 v1 = *(const float4*)(src + 4);
        As[lb][lk + 0] = v0.x; As[lb][lk + 1] = v0.y; As[lb][lk + 2] = v0.z; As[lb][lk + 3] = v0.w;
        As[lb][lk + 4] = v1.x; As[lb][lk + 5] = v1.y; As[lb][lk + 6] = v1.z; As[lb][lk + 7] = v1.w;
        const float* wsrc = Wn + (long)k0 * O;
        #pragma unroll
        for (int i = tid * 4; i < 32 * O; i += 1024)
            *(float4*)(&Ws[0][0] + i) = *(const float4*)(wsrc + i);
        __syncthreads();
        #pragma unroll
        for (int k = 0; k < 32; k++) {
            float a0 = As[trow * 4 + 0][k], a1 = As[trow * 4 + 1][k];
            float a2 = As[trow * 4 + 2][k], a3 = As[trow * 4 + 3][k];
            #pragma unroll
            for (int j = 0; j < TN; j++) {
                float w = Ws[k][tcol + 16 * j];
                acc[0][j] += a0 * w; acc[1][j] += a1 * w;
                acc[2][j] += a2 * w; acc[3][j] += a3 * w;
            }
        }
        __syncthreads();
    }
    #pragma unroll
    for (int i = 0; i < 4; i++) {
        int b = trow * 4 + i;
        #pragma unroll
        for (int j = 0; j < TN; j++) {
            int o = tcol + 16 * j;
            out[((long)b * Nn + n) * O + o] = acc[i][j] + bias[(long)n * O + o];
        }
    }
}

// ---------- small kernels ----------
static __device__ __forceinline__ float lrelu(float v) { return v >= 0.0f ? v : 0.01f * v; }
static __device__ __forceinline__ float sigmoidf(float v) { return 1.0f / (1.0f + expf(-v)); }

// out[n, j] = sum_d emb[n,d] * pool[d, j]; 32 node-rows per block, pool column in regs
__global__ void emb_matmul2(const float* __restrict__ emb, const float* __restrict__ pool,
                            float* __restrict__ out, int C)
{
    __shared__ float esm[32][EDm];
    const int tid = threadIdx.x;
    const int cb = blockIdx.x * 256 + tid;
    const int n0 = blockIdx.y * 32;
    for (int i = tid; i < 32 * EDm; i += 256)               // FIXED: full 512-elem fill
        esm[i >> 4][i & 15] = emb[(n0 + (i >> 4)) * EDm + (i & 15)];
    __syncthreads();
    if (cb >= C) return;
    float p[EDm];
    #pragma unroll
    for (int d = 0; d < EDm; d++) p[d] = pool[(long)d * C + cb];
    #pragma unroll 4
    for (int r = 0; r < 32; r++) {
        float acc = 0.f;
        #pragma unroll
        for (int d = 0; d < EDm; d++) acc += esm[r][d] * p[d];
        out[(long)(n0 + r) * C + cb] = acc;
    }
}

__global__ void transpose_batched(const float* __restrict__ in, long s_in, int ld_in,
                                  float* __restrict__ out, long s_out, int ld_out,
                                  int R, int Cc)
{
    __shared__ float tsm[32][33];
    in  += (long)blockIdx.z * s_in;
    out += (long)blockIdx.z * s_out;
    int r0 = blockIdx.x * 32, c0 = blockIdx.y * 32;
    int c = c0 + threadIdx.x;
    #pragma unroll
    for (int i = 0; i < 32; i += 8) {
        int rr = r0 + threadIdx.y + i;
        if (rr < R && c < Cc) tsm[threadIdx.y + i][threadIdx.x] = in[(long)rr * ld_in + c];
    }
    __syncthreads();
    int rr = r0 + threadIdx.x;
    #pragma unroll
    for (int i = 0; i < 32; i += 8) {
        int cc = c0 + threadIdx.y + i;
        if (cc < Cc && rr < R) out[(long)cc * ld_out + rr] = tsm[threadIdx.x][threadIdx.y + i];
    }
}

__global__ void build_xg0(const float* __restrict__ x, const float* __restrict__ st,
                          float* __restrict__ XG)
{
    long idx = (long)blockIdx.x * blockDim.x + threadIdx.x;
    if (idx >= (long)Bb * Nn * CIN) return;
    int c = (int)(idx % CIN);
    long bn = idx / CIN;
    XG[bn * KI + c] = (c < DIN) ? x[bn * DIN + c] : st[bn * DOUT + (c - DIN)];
}

__global__ void colmean_lrelu(const float* __restrict__ G, float* __restrict__ Y, int C)
{
    int b = blockIdx.x, c = threadIdx.x;
    const float* p = G + (long)b * Nn * C + c;
    float a0 = 0.f, a1 = 0.f, a2 = 0.f, a3 = 0.f;
    for (int n = 0; n < Nn; n += 4) {
        a0 += lrelu(p[(long)(n + 0) * C]); a1 += lrelu(p[(long)(n + 1) * C]);
        a2 += lrelu(p[(long)(n + 2) * C]); a3 += lrelu(p[(long)(n + 3) * C]);
    }
    Y[b * C + c] = (a0 + a1 + a2 + a3) * (1.0f / (float)Nn);
}

__global__ void att_scalar(const float* __restrict__ Y, const float* __restrict__ w1,
                           const float* __restrict__ w2, float* __restrict__ s, int C, int H)
{
    int b = blockIdx.x, j = threadIdx.x;
    float h = 0.f;
    if (j < H) {
        float acc = 0.f;
        for (int c = 0; c < C; c++) acc += Y[b * C + c] * w1[j * C + c];
        h = fmaxf(acc, 0.f) * w2[j];
    }
    #pragma unroll
    for (int off = 16; off; off >>= 1) h += __shfl_down_sync(0xffffffffu, h, off);
    if (j == 0) s[b] = sigmoidf(h);
}

__global__ void gate_combine(const float* __restrict__ G0, const float* __restrict__ G1,
                             const float* __restrict__ s0, const float* __restrict__ s1,
                             const float* __restrict__ x, const float* __restrict__ st,
                             float* __restrict__ XG, float* __restrict__ Rb)
{
    long idx = (long)blockIdx.x * blockDim.x + threadIdx.x;
    if (idx >= (long)Bb * Nn * DOUT) return;
    int o = (int)(idx % DOUT);
    long bn = idx / DOUT;
    int b = (int)(bn >> 10);
    float a0 = s0[b], a1 = s1[b];
    float zi = lrelu(G0[bn * OG + o]) * a0 + lrelu(G1[bn * OG + o]) * a1;
    float ri = lrelu(G0[bn * OG + DOUT + o]) * a0 + lrelu(G1[bn * OG + DOUT + o]) * a1;
    float r = sigmoidf(ri);
    Rb[idx] = r;
    XG[bn * KI + DIN + o] = sigmoidf(zi) * st[idx];
    if (o < DIN) XG[bn * KI + o] = x[bn * DIN + o];
}

__global__ void final_combine(const float* __restrict__ G0u, const float* __restrict__ G1u,
                              const float* __restrict__ t0, const float* __restrict__ t1,
                              const float* __restrict__ Rb, const float* __restrict__ st,
                              float* __restrict__ out)
{
    long idx = (long)blockIdx.x * blockDim.x + threadIdx.x;
    if (idx >= (long)Bb * Nn * DOUT) return;
    long bn = idx / DOUT;
    int b = (int)(bn >> 10);
    float hc = tanhf(lrelu(G0u[idx]) * t0[b] + lrelu(G1u[idx]) * t1[b]);
    float r = Rb[idx];
    out[idx] = r * st[idx] + (1.0f - r) * hc;
}

// ---------- host ----------
static inline int gemm_smem(int NT) { return 2 * (2 * 128 * RSTR + 2 * NT * RSTR) * 4; }

static inline void tc(const float* A, int lda, long sA, const float* Bm, int ldb, long sB,
                      float* C, int ldc, long sC, int M, int N, int NT, int K, int batch,
                      const float* bias, float alpha, int mI)
{
    dim3 grid(N / NT, M / 128, batch);
    switch (NT) {
    case 128:
        cudaFuncSetAttribute(mma_gemm<128>, cudaFuncAttributeMaxDynamicSharedMemorySize, gemm_smem(128));
        mma_gemm<128><<<grid, 256, gemm_smem(128)>>>(A, lda, sA, Bm, ldb, sB, C, ldc, sC, K, bias, alpha, mI);
        break;
    case 96:
        cudaFuncSetAttribute(mma_gemm<96>, cudaFuncAttributeMaxDynamicSharedMemorySize, gemm_smem(96));
        mma_gemm<96><<<grid, 256, gemm_smem(96)>>>(A, lda, sA, Bm, ldb, sB, C, ldc, sC, K, bias, alpha, mI);
        break;
    default:
        cudaFuncSetAttribute(mma_gemm<64>, cudaFuncAttributeMaxDynamicSharedMemorySize, gemm_smem(64));
        mma_gemm<64><<<grid, 256, gemm_smem(64)>>>(A, lda, sA, Bm, ldb, sB, C, ldc, sC, K, bias, alpha, mI);
        break;
    }
}

extern "C" void kernel_launch(void* const* d_in, const int* in_sizes, int n_in,
                              void* d_out, int out_size)
{
    const float* x     = (const float*)d_in[0];
    const float* state = (const float*)d_in[1];
    const float* emb   = (const float*)d_in[2];
    const float* Lm    = (const float*)d_in[3];
    const float* cheb  = (const float*)d_in[4];
    const float* gwpool = (const float*)d_in[5];
    const float* gbpool = (const float*)d_in[6];
    const float* giw = (const float*)d_in[7];
    const float* gib = (const float*)d_in[8];
    const float* ggw = (const float*)d_in[9];
    const float* ggb = (const float*)d_in[10];
    const float* ga1w1 = (const float*)d_in[11];
    const float* ga1w2 = (const float*)d_in[12];
    const float* ga2w1 = (const float*)d_in[13];
    const float* ga2w2 = (const float*)d_in[14];
    const float* uwpool = (const float*)d_in[15];
    const float* ubpool = (const float*)d_in[16];
    const float* uiw = (const float*)d_in[17];
    const float* uib = (const float*)d_in[18];
    const float* ugw = (const float*)d_in[19];
    const float* ugb = (const float*)d_in[20];
    const float* ua1w1 = (const float*)d_in[21];
    const float* ua1w2 = (const float*)d_in[22];
    const float* ua2w1 = (const float*)d_in[23];
    const float* ua2w2 = (const float*)d_in[24];
    float* out = (float*)d_out;

    float *S2, *Lt, *Wg, *Wu, *bg, *bu, *XG, *Ucm, *X0, *X0T, *XG1;
    float *G0, *G1, *Rb, *Y0, *Y1, *s0, *s1;
    cudaGetSymbolAddress((void**)&S2,  g_S2);
    cudaGetSymbolAddress((void**)&Lt,  g_Lt);
    cudaGetSymbolAddress((void**)&Wg,  g_Wg);
    cudaGetSymbolAddress((void**)&Wu,  g_Wu);
    cudaGetSymbolAddress((void**)&bg,  g_bg);
    cudaGetSymbolAddress((void**)&bu,  g_bu);
    cudaGetSymbolAddress((void**)&XG,  g_XG);
    cudaGetSymbolAddress((void**)&Ucm, g_Ucm);
    cudaGetSymbolAddress((void**)&X0,  g_X0);
    cudaGetSymbolAddress((void**)&X0T, g_X0T);
    cudaGetSymbolAddress((void**)&XG1, g_XG1);
    cudaGetSymbolAddress((void**)&G0,  g_G0);
    cudaGetSymbolAddress((void**)&G1,  g_G1);
    cudaGetSymbolAddress((void**)&Rb,  g_Rb);
    cudaGetSymbolAddress((void**)&Y0,  g_Y0);
    cudaGetSymbolAddress((void**)&Y1,  g_Y1);
    cudaGetSymbolAddress((void**)&s0,  g_s0);
    cudaGetSymbolAddress((void**)&s1,  g_s1);

    const long sXG = (long)Nn * KI;
    dim3 tb(32, 8);

    // per-node weights / biases
    emb_matmul2<<<dim3(144, 32), 256>>>(emb, gwpool, Wg, KI * OG);
    emb_matmul2<<<dim3(72, 32), 256>>>(emb, uwpool, Wu, KI * OU);
    emb_matmul2<<<dim3(1, 32), 256>>>(emb, gbpool, bg, OG);
    emb_matmul2<<<dim3(1, 32), 256>>>(emb, ubpool, bu, OU);

    // S2 = 2*L@L - I  (B operand = L^T, K-major)
    transpose_batched<<<dim3(32, 32, 1), tb>>>(Lm, 0, Nn, Lt, 0, Nn, Nn, Nn);
    tc(Lm, Nn, 0, Lt, Nn, 0, S2, Nn, 0, Nn, Nn, 128, Nn, 1, nullptr, 2.0f, 1);

    // ===== GATE =====
    build_xg0<<<((long)Bb * Nn * CIN + 255) / 256, 256>>>(x, state, XG);
    transpose_batched<<<dim3(32, 3, Bb), tb>>>(XG, sXG, KI, Ucm, (long)CIN * Nn, Nn, Nn, CIN);
    tc(Lm, Nn, 0, Ucm, Nn, (long)CIN * Nn, XG + CIN,     KI, sXG, Nn, CIN, 96, Nn, Bb, nullptr, 1.0f, 0);
    tc(S2, Nn, 0, Ucm, Nn, (long)CIN * Nn, XG + 2 * CIN, KI, sXG, Nn, CIN, 96, Nn, Bb, nullptr, 1.0f, 0);
    pernode_gconv<OG><<<Nn, 256>>>(XG, Wg, bg, G0);
    tc(XG, KI, 0, giw, CIN, 0, X0, OG, 0, Bb * Nn, OG, 128, CIN, 1, gib, 1.0f, 0);
    transpose_batched<<<dim3(32, 4, Bb), tb>>>(X0, (long)Nn * OG, OG, X0T, (long)OG * Nn, Nn, Nn, OG);
    for (int k = 0; k < KSUP; k++)
        tc(cheb + (long)k * Nn * Nn, Nn, 0, X0T, Nn, (long)OG * Nn,
           XG1 + k * OG, 3 * OG, (long)Nn * 3 * OG, Nn, OG, 128, Nn, Bb, nullptr, 1.0f, 0);
    tc(XG1, 3 * OG, 0, ggw, 3 * OG, 0, G1, OG, 0, Bb * Nn, OG, 128, 3 * OG, 1, ggb, 1.0f, 0);
    colmean_lrelu<<<Bb, OG>>>(G0, Y0, OG);
    colmean_lrelu<<<Bb, OG>>>(G1, Y1, OG);
    att_scalar<<<Bb, 32>>>(Y0, ga1w1, ga1w2, s0, OG, OG / 16);
    att_scalar<<<Bb, 32>>>(Y1, ga2w1, ga2w2, s1, OG, OG / 16);
    gate_combine<<<((long)Bb * Nn * DOUT + 255) / 256, 256>>>(G0, G1, s0, s1, x, state, XG, Rb);

    // ===== UPDATE =====
    transpose_batched<<<dim3(32, 3, Bb), tb>>>(XG, sXG, KI, Ucm, (long)CIN * Nn, Nn, Nn, CIN);
    tc(Lm, Nn, 0, Ucm, Nn, (long)CIN * Nn, XG + CIN,     KI, sXG, Nn, CIN, 96, Nn, Bb, nullptr, 1.0f, 0);
    tc(S2, Nn, 0, Ucm, Nn, (long)CIN * Nn, XG + 2 * CIN, KI, sXG, Nn, CIN, 96, Nn, Bb, nullptr, 1.0f, 0);
    pernode_gconv<OU><<<Nn, 256>>>(XG, Wu, bu, G0);
    tc(XG, KI, 0, uiw, CIN, 0, X0, OU, 0, Bb * Nn, OU, 64, CIN, 1, uib, 1.0f, 0);
    transpose_batched<<<dim3(32, 2, Bb), tb>>>(X0, (long)Nn * OU, OU, X0T, (long)OU * Nn, Nn, Nn, OU);
    for (int k = 0; k < KSUP; k++)
        tc(cheb + (long)k * Nn * Nn, Nn, 0, X0T, Nn, (long)OU * Nn,
           XG1 + k * OU, 3 * OU, (long)Nn * 3 * OU, Nn, OU, 64, Nn, Bb, nullptr, 1.0f, 0);
    tc(XG1, 3 * OU, 0, ugw, 3 * OU, 0, G1, OU, 0, Bb * Nn, OU, 64, 3 * OU, 1, ugb, 1.0f, 0);
    colmean_lrelu<<<Bb, OU>>>(G0, Y0, OU);
    colmean_lrelu<<<Bb, OU>>>(G1, Y1, OU);
    att_scalar<<<Bb, 32>>>(Y0, ua1w1, ua1w2, s0, OU, OU / 16);
    att_scalar<<<Bb, 32>>>(Y1, ua2w1, ua2w2, s1, OU, OU / 16);
    final_combine<<<((long)Bb * Nn * DOUT + 255) / 256, 256>>>(G0, G1, s0, s1, Rb, state, out);
}